// round 6
// baseline (speedup 1.0000x reference)
#include <cuda_runtime.h>

namespace {
constexpr int B = 64, T = 512, C = 384, H = 64;
constexpr int BT = B * T;
}

// Scratch for projected q, k, v (fp32, [B*T, H] each). Static device arrays —
// no allocation anywhere.
__device__ float g_q[BT * H];
__device__ float g_k[BT * H];
__device__ float g_v[BT * H];

// ---------------------------------------------------------------------------
// Kernel 1: fused QKV projection.  x:[BT,C] @ {Wq,Wk,Wv}:[C,H] -> g_q/g_k/g_v.
// 1024 blocks x 256 threads. Block handles 32 rows; x-tile cached in smem
// (48KB). Warp: 4 rows x (2 cols per W matrix) = 24 fp32 accumulators.
// W is 294KB total -> L2 resident, near-L1-hit after first warp touches it.
// ---------------------------------------------------------------------------
__global__ __launch_bounds__(256) void qkv_kernel(
    const float* __restrict__ x, const float* __restrict__ Wq,
    const float* __restrict__ Wk, const float* __restrict__ Wv) {
  __shared__ float xs[32 * C];  // 49152 B = 48KB exactly
  const int row0 = blockIdx.x * 32;

  {
    const float4* xg = reinterpret_cast<const float4*>(x + (size_t)row0 * C);
    float4* xs4 = reinterpret_cast<float4*>(xs);
    #pragma unroll
    for (int i = threadIdx.x; i < 32 * C / 4; i += 256) xs4[i] = xg[i];
  }
  __syncthreads();

  const int warp = threadIdx.x >> 5;
  const int lane = threadIdx.x & 31;
  const int r0 = warp * 4;

  float acc[4][6];
  #pragma unroll
  for (int r = 0; r < 4; ++r)
    #pragma unroll
    for (int j = 0; j < 6; ++j) acc[r][j] = 0.f;

  #pragma unroll 4
  for (int c = 0; c < C; ++c) {
    const float wq0 = __ldg(Wq + c * H + lane);
    const float wq1 = __ldg(Wq + c * H + lane + 32);
    const float wk0 = __ldg(Wk + c * H + lane);
    const float wk1 = __ldg(Wk + c * H + lane + 32);
    const float wv0 = __ldg(Wv + c * H + lane);
    const float wv1 = __ldg(Wv + c * H + lane + 32);
    #pragma unroll
    for (int r = 0; r < 4; ++r) {
      const float xv = xs[(r0 + r) * C + c];  // broadcast, conflict-free
      acc[r][0] = fmaf(xv, wq0, acc[r][0]);
      acc[r][1] = fmaf(xv, wq1, acc[r][1]);
      acc[r][2] = fmaf(xv, wk0, acc[r][2]);
      acc[r][3] = fmaf(xv, wk1, acc[r][3]);
      acc[r][4] = fmaf(xv, wv0, acc[r][4]);
      acc[r][5] = fmaf(xv, wv1, acc[r][5]);
    }
  }

  #pragma unroll
  for (int r = 0; r < 4; ++r) {
    const size_t row = (size_t)(row0 + r0 + r);
    g_q[row * H + lane]      = acc[r][0];
    g_q[row * H + lane + 32] = acc[r][1];
    g_k[row * H + lane]      = acc[r][2];
    g_k[row * H + lane + 32] = acc[r][3];
    g_v[row * H + lane]      = acc[r][4];
    g_v[row * H + lane + 32] = acc[r][5];
  }
}

// ---------------------------------------------------------------------------
// Kernel 2: flash attention, causal, 64x64 tiles.
// Grid (8 q-tiles, 64 batches) x 256 threads. Per warp: 8 q-rows; per lane:
// kv/h columns {lane, lane+32}. Online softmax with warp-shuffle reductions.
// smem (dynamic, 65792B): Qs[64][64], Ks[64][65] (padded: lanes index rows),
// Vs[64][64], Ps[64][64].
// ---------------------------------------------------------------------------
namespace {
constexpr int QS_OFF = 0;
constexpr int KS_OFF = QS_OFF + 64 * 64;   // 4096
constexpr int VS_OFF = KS_OFF + 64 * 65;   // 8256
constexpr int PS_OFF = VS_OFF + 64 * 64;   // 12352
constexpr int SMEM_FLOATS = PS_OFF + 64 * 64;  // 16448
constexpr int SMEM_BYTES = SMEM_FLOATS * 4;    // 65792
}

__global__ __launch_bounds__(256) void attn_kernel(float* __restrict__ out) {
  extern __shared__ float sm[];
  float* Qs = sm + QS_OFF;
  float* Ks = sm + KS_OFF;
  float* Vs = sm + VS_OFF;
  float* Ps = sm + PS_OFF;

  const int qt = 7 - (int)blockIdx.x;  // heavy tiles first
  const int b  = (int)blockIdx.y;
  const int warp = threadIdx.x >> 5;
  const int lane = threadIdx.x & 31;
  const int r0 = warp * 8;

  // Load Q tile, pre-scaled by 1/sqrt(H) = 0.125
  const float* qg = g_q + ((size_t)b * T + (size_t)qt * 64) * H;
  for (int i = threadIdx.x; i < 64 * 64; i += 256) Qs[i] = qg[i] * 0.125f;

  float m[8], l[8], o0[8], o1[8];
  #pragma unroll
  for (int r = 0; r < 8; ++r) {
    m[r] = -1e30f; l[r] = 0.f; o0[r] = 0.f; o1[r] = 0.f;
  }

  for (int kt = 0; kt <= qt; ++kt) {
    __syncthreads();  // Q ready (first iter) / prev PV done before overwrite
    const float* kg = g_k + ((size_t)b * T + (size_t)kt * 64) * H;
    const float* vg = g_v + ((size_t)b * T + (size_t)kt * 64) * H;
    for (int i = threadIdx.x; i < 64 * 64; i += 256) {
      Ks[(i >> 6) * 65 + (i & 63)] = kg[i];
      Vs[i] = vg[i];
    }
    __syncthreads();

    // S = Q K^T  (each lane: 8 rows x 2 kv-cols)
    float s0[8], s1[8];
    #pragma unroll
    for (int r = 0; r < 8; ++r) { s0[r] = 0.f; s1[r] = 0.f; }
    #pragma unroll 2
    for (int h = 0; h < 64; ++h) {
      const float k0 = Ks[lane * 65 + h];         // stride 65 -> conflict-free
      const float k1 = Ks[(lane + 32) * 65 + h];
      #pragma unroll
      for (int r = 0; r < 8; ++r) {
        const float qv = Qs[(r0 + r) * 64 + h];   // broadcast
        s0[r] = fmaf(qv, k0, s0[r]);
        s1[r] = fmaf(qv, k1, s1[r]);
      }
    }

    if (kt == qt) {  // diagonal tile: causal mask within tile
      #pragma unroll
      for (int r = 0; r < 8; ++r) {
        const int qi = r0 + r;
        if (lane > qi)      s0[r] = -1e30f;
        if (lane + 32 > qi) s1[r] = -1e30f;
      }
    }

    // Online softmax per row (row data lives entirely in this warp)
    #pragma unroll
    for (int r = 0; r < 8; ++r) {
      float mx = fmaxf(s0[r], s1[r]);
      #pragma unroll
      for (int off = 16; off > 0; off >>= 1)
        mx = fmaxf(mx, __shfl_xor_sync(0xffffffffu, mx, off));
      const float mnew = fmaxf(m[r], mx);
      const float alpha = __expf(m[r] - mnew);  // first iter: exp(-1e30)=0
      const float p0 = __expf(s0[r] - mnew);
      const float p1 = __expf(s1[r] - mnew);
      float ls = p0 + p1;
      #pragma unroll
      for (int off = 16; off > 0; off >>= 1)
        ls += __shfl_xor_sync(0xffffffffu, ls, off);
      m[r] = mnew;
      l[r] = l[r] * alpha + ls;
      o0[r] *= alpha;
      o1[r] *= alpha;
      Ps[(r0 + r) * 64 + lane]      = p0;  // stride-1 write, conflict-free
      Ps[(r0 + r) * 64 + lane + 32] = p1;
    }
    __syncwarp();  // warp produces & consumes its own P rows

    // O += P V  (each lane: 8 rows x 2 h-cols)
    #pragma unroll 2
    for (int j = 0; j < 64; ++j) {
      const float v0 = Vs[j * 64 + lane];        // stride-1 -> conflict-free
      const float v1 = Vs[j * 64 + lane + 32];
      #pragma unroll
      for (int r = 0; r < 8; ++r) {
        const float p = Ps[(r0 + r) * 64 + j];   // broadcast
        o0[r] = fmaf(p, v0, o0[r]);
        o1[r] = fmaf(p, v1, o1[r]);
      }
    }
  }

  float* og = out + ((size_t)b * T + (size_t)qt * 64) * H;
  #pragma unroll
  for (int r = 0; r < 8; ++r) {
    const float inv = 1.f / l[r];
    og[(r0 + r) * H + lane]      = o0[r] * inv;
    og[(r0 + r) * H + lane + 32] = o1[r] * inv;
  }
}

extern "C" void kernel_launch(void* const* d_in, const int* in_sizes, int n_in,
                              void* d_out, int out_size) {
  const float* x  = (const float*)d_in[0];
  const float* Wq = (const float*)d_in[1];
  const float* Wk = (const float*)d_in[2];
  const float* Wv = (const float*)d_in[3];
  float* out = (float*)d_out;

  qkv_kernel<<<BT / 32, 256>>>(x, Wq, Wk, Wv);

  // Not a stream-ordered op: capture-safe, idempotent, deterministic.
  cudaFuncSetAttribute(attn_kernel, cudaFuncAttributeMaxDynamicSharedMemorySize,
                       SMEM_BYTES);
  attn_kernel<<<dim3(8, B), 256, SMEM_BYTES>>>(out);
}

// round 11
// speedup vs baseline: 2.3453x; 2.3453x over previous
#include <cuda_runtime.h>
#include <cstdint>

namespace {
constexpr int B = 64, T = 512, C = 384, H = 64;
constexpr int BT = B * T;
}

// Scratch for projected q, k, v (fp32, [B*T, H] each). Static device arrays.
__device__ float g_q[BT * H];
__device__ float g_k[BT * H];
__device__ float g_v[BT * H];

// ---------------------------------------------------------------------------
// tf32 helpers
// ---------------------------------------------------------------------------
__device__ __forceinline__ uint32_t f2tf(float f) {
  uint32_t u;
  asm("cvt.rna.tf32.f32 %0, %1;" : "=r"(u) : "f"(f));
  return u;
}

// D = A(16x8,row) * B(8x8,col) + C, tf32 inputs, fp32 accum.
__device__ __forceinline__ void mma_tf32(float* d, const uint32_t* a,
                                         uint32_t b0, uint32_t b1) {
  asm("mma.sync.aligned.m16n8k8.row.col.f32.tf32.tf32.f32 "
      "{%0,%1,%2,%3}, {%4,%5,%6,%7}, {%8,%9}, {%0,%1,%2,%3};"
      : "+f"(d[0]), "+f"(d[1]), "+f"(d[2]), "+f"(d[3])
      : "r"(a[0]), "r"(a[1]), "r"(a[2]), "r"(a[3]), "r"(b0), "r"(b1));
}

// ---------------------------------------------------------------------------
// Kernel 1: fused QKV projection, tensor-core tf32.
// y[32768,192] = x[32768,384] @ [Wq|Wk|Wv][384,192].
// CTA: 256 thr = 8 warps (4 M x 2 N), CTA tile 128x192, K-chunk 32.
// smem strides: xs=36 (A banks = row*4+col, perfect), ws=200 (B banks = k*8+n).
// ---------------------------------------------------------------------------
namespace {
constexpr int XS_STRIDE = 36;   // 32 + 4  -> stride ≡ 4 (mod 32)
constexpr int WS_STRIDE = 200;  // 192 + 8 -> stride ≡ 8 (mod 32)
}

__global__ __launch_bounds__(256) void qkv_mma_kernel(
    const float* __restrict__ x, const float* __restrict__ Wq,
    const float* __restrict__ Wk, const float* __restrict__ Wv) {
  __shared__ uint32_t xs[128 * XS_STRIDE];  // 18432 B
  __shared__ uint32_t ws[32 * WS_STRIDE];   // 25600 B

  const int row0 = blockIdx.x * 128;
  const int warp = threadIdx.x >> 5;
  const int lane = threadIdx.x & 31;
  const int wm = warp >> 1;    // 0..3 -> rows wm*32..+32
  const int wn = warp & 1;     // 0..1 -> cols wn*96..+96
  const int lr = lane >> 2;    // 0..7
  const int lc = lane & 3;     // 0..3

  float acc[2][12][4];
  #pragma unroll
  for (int mt = 0; mt < 2; ++mt)
    #pragma unroll
    for (int nt = 0; nt < 12; ++nt)
      #pragma unroll
      for (int i = 0; i < 4; ++i) acc[mt][nt][i] = 0.f;

  for (int chunk = 0; chunk < 12; ++chunk) {
    const int c0 = chunk * 32;
    __syncthreads();  // protect smem from previous iteration's readers
    // stage x tile [128 x 32]
    for (int i = threadIdx.x; i < 128 * 32; i += 256) {
      const int r = i >> 5, c = i & 31;
      xs[r * XS_STRIDE + c] = f2tf(x[(size_t)(row0 + r) * C + c0 + c]);
    }
    // stage W tile [32 x 192]  (Wq|Wk|Wv)
    for (int i = threadIdx.x; i < 32 * 192; i += 256) {
      const int k = i / 192, n = i % 192;
      const float* Wsrc = (n < 64) ? Wq : (n < 128) ? Wk : Wv;
      ws[k * WS_STRIDE + n] = f2tf(Wsrc[(size_t)(c0 + k) * H + (n & 63)]);
    }
    __syncthreads();

    // A fragments for this chunk (2 m-tiles x 4 k-steps)
    uint32_t af[2][4][4];
    #pragma unroll
    for (int mt = 0; mt < 2; ++mt) {
      const int row = wm * 32 + mt * 16 + lr;
      #pragma unroll
      for (int kk = 0; kk < 4; ++kk) {
        const int col = kk * 8 + lc;
        af[mt][kk][0] = xs[row * XS_STRIDE + col];
        af[mt][kk][1] = xs[(row + 8) * XS_STRIDE + col];
        af[mt][kk][2] = xs[row * XS_STRIDE + col + 4];
        af[mt][kk][3] = xs[(row + 8) * XS_STRIDE + col + 4];
      }
    }

    #pragma unroll
    for (int nt = 0; nt < 12; ++nt) {
      const int n = wn * 96 + nt * 8 + lr;
      #pragma unroll
      for (int kk = 0; kk < 4; ++kk) {
        const int k = kk * 8 + lc;
        const uint32_t b0 = ws[k * WS_STRIDE + n];
        const uint32_t b1 = ws[(k + 4) * WS_STRIDE + n];
        mma_tf32(acc[0][nt], af[0][kk], b0, b1);
        mma_tf32(acc[1][nt], af[1][kk], b0, b1);
      }
    }
  }

  // epilogue: scatter to g_q / g_k / g_v (float2 stores, 32B per quad-row)
  #pragma unroll
  for (int mt = 0; mt < 2; ++mt) {
    const int rbase = row0 + wm * 32 + mt * 16 + lr;
    #pragma unroll
    for (int nt = 0; nt < 12; ++nt) {
      const int n0 = wn * 96 + nt * 8 + lc * 2;
      float* dst = (n0 < 64) ? g_q : (n0 < 128) ? g_k : g_v;
      const int nn = n0 & 63;
      *reinterpret_cast<float2*>(&dst[(size_t)rbase * H + nn]) =
          make_float2(acc[mt][nt][0], acc[mt][nt][1]);
      *reinterpret_cast<float2*>(&dst[(size_t)(rbase + 8) * H + nn]) =
          make_float2(acc[mt][nt][2], acc[mt][nt][3]);
    }
  }
}

// ---------------------------------------------------------------------------
// Kernel 2: flash attention, causal, tensor-core tf32, 64x64 tiles.
// Grid (8 qt, 64 b) x 128 thr (4 warps). Warp w owns q-rows [w*16, w*16+16).
// Q A-fragments hoisted into registers once. Conflict-free operand strides:
//   Qs/Ks/Ps stride 68 (≡4 mod 32), Vs stride 72 (≡8 mod 32).
// ---------------------------------------------------------------------------
namespace {
constexpr int QS_OFF = 0;
constexpr int KS_OFF = QS_OFF + 64 * 68;
constexpr int VS_OFF = KS_OFF + 64 * 68;
constexpr int PS_OFF = VS_OFF + 64 * 72;
constexpr int ATTN_SMEM_WORDS = PS_OFF + 64 * 68;
constexpr int ATTN_SMEM_BYTES = ATTN_SMEM_WORDS * 4;  // 70656
}

__global__ __launch_bounds__(128) void attn_mma_kernel(float* __restrict__ out) {
  extern __shared__ uint32_t sm[];
  uint32_t* Qs = sm + QS_OFF;  // [64][68]
  uint32_t* Ks = sm + KS_OFF;  // [64][68]
  uint32_t* Vs = sm + VS_OFF;  // [64][72]
  uint32_t* Ps = sm + PS_OFF;  // [64][68]

  const int qt = 7 - (int)blockIdx.x;  // heavy tiles first
  const int b = (int)blockIdx.y;
  const int warp = threadIdx.x >> 5;
  const int lane = threadIdx.x & 31;
  const int lr = lane >> 2, lc = lane & 3;
  const int qrow = warp * 16 + lr;  // local q row of fragment group 0

  // stage Q (pre-scaled by 1/8), tf32
  const float* qg = g_q + ((size_t)b * T + (size_t)qt * 64) * H;
  for (int i = threadIdx.x; i < 64 * 64; i += 128)
    Qs[(i >> 6) * 68 + (i & 63)] = f2tf(qg[i] * 0.125f);
  __syncthreads();

  // hoist Q A-fragments (8 k-steps x 4 regs)
  uint32_t aq[8][4];
  #pragma unroll
  for (int kk = 0; kk < 8; ++kk) {
    const int c = kk * 8 + lc;
    aq[kk][0] = Qs[qrow * 68 + c];
    aq[kk][1] = Qs[(qrow + 8) * 68 + c];
    aq[kk][2] = Qs[qrow * 68 + c + 4];
    aq[kk][3] = Qs[(qrow + 8) * 68 + c + 4];
  }

  float m[2] = {-1e30f, -1e30f}, l[2] = {0.f, 0.f};
  float o[8][4];
  #pragma unroll
  for (int nt = 0; nt < 8; ++nt)
    #pragma unroll
    for (int i = 0; i < 4; ++i) o[nt][i] = 0.f;

  for (int kt = 0; kt <= qt; ++kt) {
    __syncthreads();  // protect Ks/Vs reuse
    const float* kg = g_k + ((size_t)b * T + (size_t)kt * 64) * H;
    const float* vg = g_v + ((size_t)b * T + (size_t)kt * 64) * H;
    for (int i = threadIdx.x; i < 64 * 64; i += 128) {
      const int r = i >> 6, c = i & 63;
      Ks[r * 68 + c] = f2tf(kg[i]);
      Vs[r * 72 + c] = f2tf(vg[i]);
    }
    __syncthreads();

    // S = Q K^T : s[nt] covers kv cols [nt*8, nt*8+8)
    float s[8][4];
    #pragma unroll
    for (int nt = 0; nt < 8; ++nt)
      #pragma unroll
      for (int i = 0; i < 4; ++i) s[nt][i] = 0.f;

    #pragma unroll
    for (int nt = 0; nt < 8; ++nt) {
      const int kv = nt * 8 + lr;
      #pragma unroll
      for (int kk = 0; kk < 8; ++kk) {
        const int h = kk * 8 + lc;
        mma_tf32(s[nt], aq[kk], Ks[kv * 68 + h], Ks[kv * 68 + h + 4]);
      }
    }

    if (kt == qt) {  // causal mask inside diagonal tile
      #pragma unroll
      for (int nt = 0; nt < 8; ++nt) {
        const int kv0 = nt * 8 + lc * 2;
        if (kv0 > qrow)         s[nt][0] = -1e30f;
        if (kv0 + 1 > qrow)     s[nt][1] = -1e30f;
        if (kv0 > qrow + 8)     s[nt][2] = -1e30f;
        if (kv0 + 1 > qrow + 8) s[nt][3] = -1e30f;
      }
    }

    // online softmax per fragment row-group (rows qrow, qrow+8)
    #pragma unroll
    for (int g = 0; g < 2; ++g) {
      float mx = -1e30f;
      #pragma unroll
      for (int nt = 0; nt < 8; ++nt)
        mx = fmaxf(mx, fmaxf(s[nt][2 * g], s[nt][2 * g + 1]));
      mx = fmaxf(mx, __shfl_xor_sync(0xffffffffu, mx, 1));
      mx = fmaxf(mx, __shfl_xor_sync(0xffffffffu, mx, 2));
      const float mnew = fmaxf(m[g], mx);
      const float alpha = __expf(m[g] - mnew);
      float ls = 0.f;
      #pragma unroll
      for (int nt = 0; nt < 8; ++nt) {
        const float p0 = __expf(s[nt][2 * g] - mnew);
        const float p1 = __expf(s[nt][2 * g + 1] - mnew);
        s[nt][2 * g] = p0;
        s[nt][2 * g + 1] = p1;
        ls += p0 + p1;
      }
      ls += __shfl_xor_sync(0xffffffffu, ls, 1);
      ls += __shfl_xor_sync(0xffffffffu, ls, 2);
      m[g] = mnew;
      l[g] = l[g] * alpha + ls;
      #pragma unroll
      for (int nt = 0; nt < 8; ++nt) {
        o[nt][2 * g] *= alpha;
        o[nt][2 * g + 1] *= alpha;
      }
    }

    // store P (tf32) into warp-private rows of Ps
    #pragma unroll
    for (int nt = 0; nt < 8; ++nt) {
      const int col = nt * 8 + lc * 2;
      Ps[qrow * 68 + col]       = f2tf(s[nt][0]);
      Ps[qrow * 68 + col + 1]   = f2tf(s[nt][1]);
      Ps[(qrow + 8) * 68 + col]     = f2tf(s[nt][2]);
      Ps[(qrow + 8) * 68 + col + 1] = f2tf(s[nt][3]);
    }
    __syncwarp();  // warp produces & consumes its own P rows

    // O += P V : o[nt] covers h cols [nt*8, nt*8+8)
    #pragma unroll
    for (int kk = 0; kk < 8; ++kk) {
      uint32_t ap[4];
      const int c = kk * 8 + lc;
      ap[0] = Ps[qrow * 68 + c];
      ap[1] = Ps[(qrow + 8) * 68 + c];
      ap[2] = Ps[qrow * 68 + c + 4];
      ap[3] = Ps[(qrow + 8) * 68 + c + 4];
      const int kv = kk * 8 + lc;
      #pragma unroll
      for (int nt = 0; nt < 8; ++nt) {
        const int h = nt * 8 + lr;
        mma_tf32(o[nt], ap, Vs[kv * 72 + h], Vs[(kv + 4) * 72 + h]);
      }
    }
  }

  // epilogue: normalize and store
  float* og = out + ((size_t)b * T + (size_t)qt * 64) * H;
  const float inv0 = 1.f / l[0], inv1 = 1.f / l[1];
  #pragma unroll
  for (int nt = 0; nt < 8; ++nt) {
    const int h = nt * 8 + lc * 2;
    *reinterpret_cast<float2*>(&og[(size_t)qrow * H + h]) =
        make_float2(o[nt][0] * inv0, o[nt][1] * inv0);
    *reinterpret_cast<float2*>(&og[(size_t)(qrow + 8) * H + h]) =
        make_float2(o[nt][2] * inv1, o[nt][3] * inv1);
  }
}

extern "C" void kernel_launch(void* const* d_in, const int* in_sizes, int n_in,
                              void* d_out, int out_size) {
  const float* x = (const float*)d_in[0];
  const float* Wq = (const float*)d_in[1];
  const float* Wk = (const float*)d_in[2];
  const float* Wv = (const float*)d_in[3];
  float* out = (float*)d_out;

  qkv_mma_kernel<<<BT / 128, 256>>>(x, Wq, Wk, Wv);

  // Not a stream-ordered op: capture-safe, idempotent, deterministic.
  cudaFuncSetAttribute(attn_mma_kernel,
                       cudaFuncAttributeMaxDynamicSharedMemorySize,
                       ATTN_SMEM_BYTES);
  attn_mma_kernel<<<dim3(8, B), 128, ATTN_SMEM_BYTES>>>(out);
}